// round 6
// baseline (speedup 1.0000x reference)
#include <cuda_runtime.h>

// dims (4,4,32,256,256) fp32 -> BC=16 volumes of DD*HH*WW
#define DD 32
#define HH 256
#define WW 256
#define TY 4
#define NR (TY + 2)     // 6 rows (tile + y-halo)
#define ZT 8            // output planes per z-chunk
#define XSEG 128        // x-width per warp (32 lanes x float4)
#define PLANE (HH * WW)

__device__ __forceinline__ float4 f4max(float4 a, float4 b) {
    return make_float4(fmaxf(a.x, b.x), fmaxf(a.y, b.y),
                       fmaxf(a.z, b.z), fmaxf(a.w, b.w));
}

__global__ __launch_bounds__(128, 4)
void nms3d_kernel(const float* __restrict__ in, float* __restrict__ out) {
    const int gw   = blockIdx.x * 4 + (threadIdx.x >> 5);   // global warp-tile id
    const int lane = threadIdx.x & 31;

    const int xs = (gw & 1) * XSEG;          // 0 or 128
    const int y0 = ((gw >> 1) & 63) * TY;    // 0..252
    const int z0 = ((gw >> 7) & 3) * ZT;     // 0,8,16,24
    const int bc = gw >> 9;                  // 0..15
    const int x0 = xs + 4 * lane;

    const float* vol   = in  + (size_t)bc * (DD * PLANE);
    float*       ovol  = out + (size_t)bc * (DD * PLANE);
    const float* baseC = vol + x0;
    const float* baseL = vol + max(xs - 1, 0);           // left extra (x = xs-1)
    const float* baseR = vol + min(xs + XSEG, WW - 1);   // right extra (x = xs+128)
    float*       obaseC = ovol + x0;

    int yoff[NR];
#pragma unroll
    for (int r = 0; r < NR; ++r) {
        int y = y0 - 1 + r; y = min(max(y, 0), HH - 1);
        yoff[r] = y * WW;
    }
    float frow[TY];
#pragma unroll
    for (int j = 0; j < TY; ++j)
        frow[j] = ((y0 + j) == 0 || (y0 + j) == HH - 1) ? 0.0f : 1.0f;

    const float mx0 = (x0 == 0) ? 0.0f : 1.0f;
    const float mx3 = (x0 + 3 == WW - 1) ? 0.0f : 1.0f;
    const bool  l0  = (lane == 0);
    const bool  l31 = (lane == 31);

    float4 pref[NR];
    float  eL[NR], eR[NR];
    float4 VA[TY], VB[TY], MPC[TY];

    // load plane Z (z-clamped) into pref/eL/eR
#define PREFZ(Z)                                                              \
    do {                                                                      \
        int zz = (Z); zz = min(max(zz, 0), DD - 1);                           \
        const size_t zf = (size_t)zz * PLANE;                                 \
        _Pragma("unroll")                                                     \
        for (int r = 0; r < NR; ++r) {                                        \
            pref[r] = __ldg((const float4*)(baseC + zf + yoff[r]));           \
            eL[r]   = __ldg(baseL + zf + yoff[r]);                            \
            eR[r]   = __ldg(baseR + zf + yoff[r]);                            \
        }                                                                     \
    } while (0)

    // consume pref: VF[j] = 3x3 xy-window max; SZ[j] = center-plane 8-nb max
#define RMAX(VF, SZ, DOSZ)                                                    \
    do {                                                                      \
        _Pragma("unroll")                                                     \
        for (int r = 0; r < NR; ++r) {                                        \
            float4 w  = pref[r];                                              \
            float wm1 = __shfl_up_sync(0xffffffffu, w.w, 1);                  \
            if (l0)  wm1 = eL[r];                                             \
            float w4  = __shfl_down_sync(0xffffffffu, w.x, 1);                \
            if (l31) w4  = eR[r];                                             \
            float p01 = fmaxf(w.x, w.y);                                      \
            float p12 = fmaxf(w.y, w.z);                                      \
            float p23 = fmaxf(w.z, w.w);                                      \
            float4 m3r = make_float4(fmaxf(wm1, p01), fmaxf(p01, w.z),        \
                                     fmaxf(p12, w.w), fmaxf(p23, w4));        \
            if (r >= 2) {                                                     \
                VF[r - 2] = f4max(VF[r - 2], m3r);                            \
                if (DOSZ) SZ[r - 2] = f4max(SZ[r - 2], m3r);                  \
            }                                                                 \
            if (r >= 1 && r <= TY) {                                          \
                VF[r - 1] = f4max(VF[r - 1], m3r);                            \
                if (DOSZ) {                                                   \
                    float4 m2r = make_float4(fmaxf(wm1, w.y), fmaxf(w.x, w.z),\
                                             fmaxf(w.y, w.w), fmaxf(w.z, w4));\
                    SZ[r - 1] = f4max(SZ[r - 1], m2r);                        \
                }                                                             \
            }                                                                 \
            if (r < TY) { VF[r] = m3r; if (DOSZ) SZ[r] = m3r; }               \
        }                                                                     \
    } while (0)

    // one z-step: rowmax plane zo+1 (fresh -> VF), prefetch zo+2, emit zo
#define STEP(i, VF, VP)                                                       \
    do {                                                                      \
        float4 szcf[TY];                                                      \
        RMAX(VF, szcf, 1);                                                    \
        if ((i) < ZT - 1) PREFZ(z0 + (i) + 2);                                \
        const int zo = z0 + (i);                                              \
        const float zval = ((zo == 0) || (zo == DD - 1)) ? 0.0f : 1.0f;       \
        const size_t zoffC = (size_t)zo * PLANE;                              \
        _Pragma("unroll")                                                     \
        for (int j = 0; j < TY; ++j) {                                        \
            float4 c = __ldg((const float4*)(baseC + zoffC + yoff[j + 1]));   \
            float4 M = f4max(MPC[j], VF[j]);                                  \
            float mrow = zval * frow[j];                                      \
            float4 o;                                                         \
            o.x = ((c.x > M.x) ? c.x : 0.0f) * mrow * mx0;                    \
            o.y = ((c.y > M.y) ? c.y : 0.0f) * mrow;                          \
            o.z = ((c.z > M.z) ? c.z : 0.0f) * mrow;                          \
            o.w = ((c.w > M.w) ? c.w : 0.0f) * mrow * mx3;                    \
            *(float4*)(obaseC + zoffC + yoff[j + 1]) = o;                     \
            MPC[j] = f4max(VP[j], szcf[j]);                                   \
        }                                                                     \
    } while (0)

    // ---- prologue ----
    {
        float4 szP[TY];
        PREFZ(z0 - 1);
        RMAX(VA, szP, 0);          // VA = v3[plane z0-1]
        PREFZ(z0);
        RMAX(VB, szP, 1);          // VB = v3[plane z0], szP = szc[plane z0]
#pragma unroll
        for (int j = 0; j < TY; ++j)
            MPC[j] = f4max(VA[j], szP[j]);
        PREFZ(z0 + 1);
    }

    // ---- 8 steps, alternating fresh/prev v3 arrays ----
    STEP(0, VA, VB);
    STEP(1, VB, VA);
    STEP(2, VA, VB);
    STEP(3, VB, VA);
    STEP(4, VA, VB);
    STEP(5, VB, VA);
    STEP(6, VA, VB);
    STEP(7, VB, VA);
}

extern "C" void kernel_launch(void* const* d_in, const int* in_sizes, int n_in,
                              void* d_out, int out_size) {
    const float* x = (const float*)d_in[0];
    float* out = (float*)d_out;
    (void)in_sizes; (void)n_in; (void)out_size;
    // warp-tiles: 2 xsegs * 64 ytiles * 4 zchunks * 16 volumes = 8192 -> /4 warps
    nms3d_kernel<<<2048, 128>>>(x, out);
}

// round 7
// speedup vs baseline: 1.0558x; 1.0558x over previous
#include <cuda_runtime.h>

// dims (4,4,32,256,256) fp32 -> BC=16 volumes of DD*HH*WW
#define DD 32
#define HH 256
#define WW 256
#define TY 2
#define NR (TY + 2)     // 4 rows (tile + y-halo)
#define ZT 8            // output planes per z-chunk
#define XSEG 128        // x-width per warp (32 lanes x float4)
#define PLANE (HH * WW)

__device__ __forceinline__ float4 f4max(float4 a, float4 b) {
    return make_float4(fmaxf(a.x, b.x), fmaxf(a.y, b.y),
                       fmaxf(a.z, b.z), fmaxf(a.w, b.w));
}

__global__ __launch_bounds__(128, 6)
void nms3d_kernel(const float* __restrict__ in, float* __restrict__ out) {
    const int gw   = blockIdx.x * 4 + (threadIdx.x >> 5);  // global warp-tile id
    const int lane = threadIdx.x & 31;

    // 1b xseg | 7b ytile | 2b zchunk | 4b bc  = 16384 warp tiles
    const int xs = (gw & 1) * XSEG;
    const int y0 = ((gw >> 1) & 127) * TY;
    const int z0 = ((gw >> 8) & 3) * ZT;
    const int bc = gw >> 10;
    const int x0 = xs + 4 * lane;

    const float* vol    = in  + (size_t)bc * (DD * PLANE);
    float*       ovol   = out + (size_t)bc * (DD * PLANE);
    const float* baseC  = vol + x0;
    const float* baseL  = vol + max(xs - 1, 0);          // x = xs-1 (clamped)
    const float* baseR  = vol + min(xs + XSEG, WW - 1);  // x = xs+128 (clamped)
    float*       obaseC = ovol + x0;

    int yoff[NR];
#pragma unroll
    for (int r = 0; r < NR; ++r) {
        int y = y0 - 1 + r; y = min(max(y, 0), HH - 1);
        yoff[r] = y * WW;
    }

    // pre-folded output masks: row edge * x edge
    const float mx0 = (x0 == 0) ? 0.0f : 1.0f;
    const float mx3 = (x0 + 3 == WW - 1) ? 0.0f : 1.0f;
    const float fr0 = (y0 == 0) ? 0.0f : 1.0f;          // row y0
    const float fr1 = (y0 + 1 == HH - 1) ? 0.0f : 1.0f; // row y0+1
    const float4 mf0 = make_float4(fr0 * mx0, fr0, fr0, fr0 * mx3);
    const float4 mf1 = make_float4(fr1 * mx0, fr1, fr1, fr1 * mx3);

    const bool l0  = (lane == 0);
    const bool l31 = (lane == 31);

    float4 pref[NR];
    float  eL[NR], eR[NR];
    float4 VA[TY], VB[TY], MPC[TY];

    // load plane Z (z-clamped) into pref/eL/eR
#define PREFZ(Z)                                                              \
    do {                                                                      \
        int zz = (Z); zz = min(max(zz, 0), DD - 1);                           \
        const size_t zf = (size_t)zz * PLANE;                                 \
        _Pragma("unroll")                                                     \
        for (int r = 0; r < NR; ++r) {                                        \
            pref[r] = __ldg((const float4*)(baseC + zf + yoff[r]));           \
            eL[r]   = __ldg(baseL + zf + yoff[r]);                            \
            eR[r]   = __ldg(baseR + zf + yoff[r]);                            \
        }                                                                     \
    } while (0)

    // consume pref: VF[j] = 3x3 xy-window max; SZ[j] = center-plane 8-nb max
#define RMAX(VF, SZ)                                                          \
    do {                                                                      \
        float4 m3r[NR]; float4 m2r1, m2r2;                                    \
        _Pragma("unroll")                                                     \
        for (int r = 0; r < NR; ++r) {                                        \
            float4 w  = pref[r];                                              \
            float wm1 = __shfl_up_sync(0xffffffffu, w.w, 1);                  \
            if (l0)  wm1 = eL[r];                                             \
            float w4  = __shfl_down_sync(0xffffffffu, w.x, 1);                \
            if (l31) w4 = eR[r];                                              \
            float p01 = fmaxf(w.x, w.y);                                      \
            float p12 = fmaxf(w.y, w.z);                                      \
            float p23 = fmaxf(w.z, w.w);                                      \
            m3r[r] = make_float4(fmaxf(wm1, p01), fmaxf(p01, w.z),            \
                                 fmaxf(p12, w.w), fmaxf(p23, w4));            \
            if (r == 1) m2r1 = make_float4(fmaxf(wm1, w.y), fmaxf(w.x, w.z),  \
                                           fmaxf(w.y, w.w), fmaxf(w.z, w4));  \
            if (r == 2) m2r2 = make_float4(fmaxf(wm1, w.y), fmaxf(w.x, w.z),  \
                                           fmaxf(w.y, w.w), fmaxf(w.z, w4));  \
        }                                                                     \
        VF[0] = f4max(f4max(m3r[0], m3r[1]), m3r[2]);                         \
        VF[1] = f4max(f4max(m3r[1], m3r[2]), m3r[3]);                         \
        SZ[0] = f4max(f4max(m3r[0], m2r1), m3r[2]);                           \
        SZ[1] = f4max(f4max(m3r[1], m2r2), m3r[3]);                           \
    } while (0)

    // one z-step: center loads hoisted first, rowmax fresh plane, prefetch
    // plane zo+2, emit plane zo, rotate MPC
#define STEP(i, VF, VP)                                                       \
    do {                                                                      \
        const int zo = z0 + (i);                                              \
        const size_t zoffC = (size_t)zo * PLANE;                              \
        float4 c0 = __ldg((const float4*)(baseC + zoffC + yoff[1]));          \
        float4 c1 = __ldg((const float4*)(baseC + zoffC + yoff[2]));          \
        float4 szcf[TY];                                                      \
        RMAX(VF, szcf);                                                       \
        if ((i) < ZT - 1) PREFZ(z0 + (i) + 2);                                \
        if ((zo == 0) || (zo == DD - 1)) {                                    \
            float4 zq = make_float4(0.f, 0.f, 0.f, 0.f);                      \
            *(float4*)(obaseC + zoffC + yoff[1]) = zq;                        \
            *(float4*)(obaseC + zoffC + yoff[2]) = zq;                        \
        } else {                                                              \
            float4 M0 = f4max(MPC[0], VF[0]);                                 \
            float4 M1 = f4max(MPC[1], VF[1]);                                 \
            float4 o0, o1;                                                    \
            o0.x = ((c0.x > M0.x) ? c0.x : 0.0f) * mf0.x;                     \
            o0.y = ((c0.y > M0.y) ? c0.y : 0.0f) * mf0.y;                     \
            o0.z = ((c0.z > M0.z) ? c0.z : 0.0f) * mf0.z;                     \
            o0.w = ((c0.w > M0.w) ? c0.w : 0.0f) * mf0.w;                     \
            o1.x = ((c1.x > M1.x) ? c1.x : 0.0f) * mf1.x;                     \
            o1.y = ((c1.y > M1.y) ? c1.y : 0.0f) * mf1.y;                     \
            o1.z = ((c1.z > M1.z) ? c1.z : 0.0f) * mf1.z;                     \
            o1.w = ((c1.w > M1.w) ? c1.w : 0.0f) * mf1.w;                     \
            *(float4*)(obaseC + zoffC + yoff[1]) = o0;                        \
            *(float4*)(obaseC + zoffC + yoff[2]) = o1;                        \
        }                                                                     \
        MPC[0] = f4max(VP[0], szcf[0]);                                       \
        MPC[1] = f4max(VP[1], szcf[1]);                                       \
    } while (0)

    // ---- prologue ----
    {
        float4 szc0[TY];
        PREFZ(z0 - 1);
        RMAX(VA, szc0);            // VA = v3[z0-1] (szc0 discarded)
        PREFZ(z0);
        RMAX(VB, szc0);            // VB = v3[z0], szc0 = szc[z0]
        MPC[0] = f4max(VA[0], szc0[0]);
        MPC[1] = f4max(VA[1], szc0[1]);
        PREFZ(z0 + 1);
    }

    // ---- 8 steps, ping-pong v3 arrays ----
    STEP(0, VA, VB);
    STEP(1, VB, VA);
    STEP(2, VA, VB);
    STEP(3, VB, VA);
    STEP(4, VA, VB);
    STEP(5, VB, VA);
    STEP(6, VA, VB);
    STEP(7, VB, VA);
}

extern "C" void kernel_launch(void* const* d_in, const int* in_sizes, int n_in,
                              void* d_out, int out_size) {
    const float* x = (const float*)d_in[0];
    float* out = (float*)d_out;
    (void)in_sizes; (void)n_in; (void)out_size;
    // 16384 warp-tiles / 4 warps per block
    nms3d_kernel<<<4096, 128>>>(x, out);
}

// round 9
// speedup vs baseline: 1.2405x; 1.1749x over previous
#include <cuda_runtime.h>

// dims (4,4,32,256,256) fp32 -> BC=16 volumes of DD*HH*WW
#define DD 32
#define HH 256
#define WW 256
#define TY 2
#define NR (TY + 2)     // 4 rows (tile + y-halo)
#define ZT 8            // output planes per z-chunk
#define XSEG 128        // x-width per warp (32 lanes x float4)
#define PLANE (HH * WW)

__device__ __forceinline__ float4 f4max(float4 a, float4 b) {
    return make_float4(fmaxf(a.x, b.x), fmaxf(a.y, b.y),
                       fmaxf(a.z, b.z), fmaxf(a.w, b.w));
}

__global__ __launch_bounds__(128, 5)
void nms3d_kernel(const float* __restrict__ in, float* __restrict__ out) {
    const int gw   = blockIdx.x * 4 + (threadIdx.x >> 5);  // global warp-tile id
    const int lane = threadIdx.x & 31;

    // 1b xseg | 7b ytile | 2b zchunk | 4b bc  = 16384 warp tiles
    const int xs = (gw & 1) * XSEG;
    const int y0 = ((gw >> 1) & 127) * TY;
    const int z0 = ((gw >> 8) & 3) * ZT;
    const int bc = gw >> 10;
    const int x0 = xs + 4 * lane;

    const float* vol    = in  + (size_t)bc * (DD * PLANE);
    float*       ovol   = out + (size_t)bc * (DD * PLANE);
    const float* baseC  = vol + x0;
    float*       obaseC = ovol + x0;
    // one edge pointer per lane: lane31 reads the right seam, all others left
    const bool l0  = (lane == 0);
    const bool l31 = (lane == 31);
    const float* baseE  = vol + (l31 ? min(xs + XSEG, WW - 1) : max(xs - 1, 0));

    int yoff[NR];
#pragma unroll
    for (int r = 0; r < NR; ++r) {
        int y = y0 - 1 + r; y = min(max(y, 0), HH - 1);
        yoff[r] = y * WW;
    }

    // output masks: row edge * x edge, folded per component
    const float mx0 = (x0 == 0) ? 0.0f : 1.0f;
    const float mx3 = (x0 + 3 == WW - 1) ? 0.0f : 1.0f;
    const float fr0 = (y0 == 0) ? 0.0f : 1.0f;
    const float fr1 = (y0 + 1 == HH - 1) ? 0.0f : 1.0f;

    float4 pA[NR], pB[NR];
    float  eA[NR], eB[NR];
    float4 VA[TY], VB[TY], MPC[TY];

    // load plane Z (z-clamped) into buffer P/E
#define PREFZ(Z, P, E)                                                        \
    do {                                                                      \
        int zz = (Z); zz = min(max(zz, 0), DD - 1);                           \
        const size_t zf = (size_t)zz * PLANE;                                 \
        _Pragma("unroll")                                                     \
        for (int r = 0; r < NR; ++r) {                                        \
            P[r] = __ldg((const float4*)(baseC + zf + yoff[r]));              \
            E[r] = __ldg(baseE + zf + yoff[r]);                               \
        }                                                                     \
    } while (0)

    // consume buffer P/E: VF[j] = 3x3 xy-window max; SZ[j] = center 8-nb max
#define RMAX(P, E, VF, SZ, DOSZ)                                              \
    do {                                                                      \
        float4 m3r[NR]; float4 m2r1, m2r2;                                    \
        _Pragma("unroll")                                                     \
        for (int r = 0; r < NR; ++r) {                                        \
            float4 w  = P[r];                                                 \
            float wm1 = __shfl_up_sync(0xffffffffu, w.w, 1);                  \
            if (l0)  wm1 = E[r];                                              \
            float w4  = __shfl_down_sync(0xffffffffu, w.x, 1);                \
            if (l31) w4 = E[r];                                               \
            float p01 = fmaxf(w.x, w.y);                                      \
            float p12 = fmaxf(w.y, w.z);                                      \
            float p23 = fmaxf(w.z, w.w);                                      \
            m3r[r] = make_float4(fmaxf(wm1, p01), fmaxf(p01, w.z),            \
                                 fmaxf(p12, w.w), fmaxf(p23, w4));            \
            if (DOSZ && r == 1)                                               \
                m2r1 = make_float4(fmaxf(wm1, w.y), fmaxf(w.x, w.z),          \
                                   fmaxf(w.y, w.w), fmaxf(w.z, w4));          \
            if (DOSZ && r == 2)                                               \
                m2r2 = make_float4(fmaxf(wm1, w.y), fmaxf(w.x, w.z),          \
                                   fmaxf(w.y, w.w), fmaxf(w.z, w4));          \
        }                                                                     \
        VF[0] = f4max(f4max(m3r[0], m3r[1]), m3r[2]);                         \
        VF[1] = f4max(f4max(m3r[1], m3r[2]), m3r[3]);                         \
        if (DOSZ) {                                                           \
            SZ[0] = f4max(f4max(m3r[0], m2r1), m3r[2]);                       \
            SZ[1] = f4max(f4max(m3r[1], m2r2), m3r[3]);                       \
        }                                                                     \
    } while (0)

    // step i: emit plane zo=z0+i; consume buffer P (holds plane zo+1, issued
    // two steps ago), then refill P with plane zo+3 (consumed two steps later)
#define STEP(i, P, E, VF, VP)                                                 \
    do {                                                                      \
        const int zo = z0 + (i);                                              \
        const size_t zoffC = (size_t)zo * PLANE;                              \
        float4 c0 = __ldg((const float4*)(baseC + zoffC + yoff[1]));          \
        float4 c1 = __ldg((const float4*)(baseC + zoffC + yoff[2]));          \
        float4 szcf[TY];                                                      \
        RMAX(P, E, VF, szcf, 1);                                              \
        if ((i) < ZT - 2) PREFZ(z0 + (i) + 3, P, E);                          \
        if ((zo == 0) || (zo == DD - 1)) {                                    \
            float4 zq = make_float4(0.f, 0.f, 0.f, 0.f);                      \
            *(float4*)(obaseC + zoffC + yoff[1]) = zq;                        \
            *(float4*)(obaseC + zoffC + yoff[2]) = zq;                        \
        } else {                                                              \
            float4 M0 = f4max(MPC[0], VF[0]);                                 \
            float4 M1 = f4max(MPC[1], VF[1]);                                 \
            float4 o0, o1;                                                    \
            o0.x = ((c0.x > M0.x) ? c0.x : 0.0f) * fr0 * mx0;                 \
            o0.y = ((c0.y > M0.y) ? c0.y : 0.0f) * fr0;                       \
            o0.z = ((c0.z > M0.z) ? c0.z : 0.0f) * fr0;                       \
            o0.w = ((c0.w > M0.w) ? c0.w : 0.0f) * fr0 * mx3;                 \
            o1.x = ((c1.x > M1.x) ? c1.x : 0.0f) * fr1 * mx0;                 \
            o1.y = ((c1.y > M1.y) ? c1.y : 0.0f) * fr1;                       \
            o1.z = ((c1.z > M1.z) ? c1.z : 0.0f) * fr1;                       \
            o1.w = ((c1.w > M1.w) ? c1.w : 0.0f) * fr1 * mx3;                 \
            *(float4*)(obaseC + zoffC + yoff[1]) = o0;                        \
            *(float4*)(obaseC + zoffC + yoff[2]) = o1;                        \
        }                                                                     \
        MPC[0] = f4max(VP[0], szcf[0]);                                       \
        MPC[1] = f4max(VP[1], szcf[1]);                                       \
    } while (0)

    // ---- prologue: planes z0-1, z0 consumed; z0+1 (A) and z0+2 (B) in flight
    {
        float4 szc0[TY];
        PREFZ(z0 - 1, pA, eA);
        RMAX(pA, eA, VA, szc0, 0);     // VA = v3[z0-1]
        PREFZ(z0, pB, eB);
        RMAX(pB, eB, VB, szc0, 1);     // VB = v3[z0], szc0 = szc[z0]
        MPC[0] = f4max(VA[0], szc0[0]);
        MPC[1] = f4max(VA[1], szc0[1]);
        PREFZ(z0 + 1, pA, eA);
        PREFZ(z0 + 2, pB, eB);
    }

    // ---- 8 steps: buffers and v3 arrays ping-pong together ----
    STEP(0, pA, eA, VA, VB);
    STEP(1, pB, eB, VB, VA);
    STEP(2, pA, eA, VA, VB);
    STEP(3, pB, eB, VB, VA);
    STEP(4, pA, eA, VA, VB);
    STEP(5, pB, eB, VB, VA);
    STEP(6, pA, eA, VA, VB);
    STEP(7, pB, eB, VB, VA);
}

extern "C" void kernel_launch(void* const* d_in, const int* in_sizes, int n_in,
                              void* d_out, int out_size) {
    const float* x = (const float*)d_in[0];
    float* out = (float*)d_out;
    (void)in_sizes; (void)n_in; (void)out_size;
    // 16384 warp-tiles / 4 warps per block
    nms3d_kernel<<<4096, 128>>>(x, out);
}